// round 8
// baseline (speedup 1.0000x reference)
#include <cuda_runtime.h>
#include <cuda_bf16.h>
#include <cstdint>

#define HH 512
#define AA 80
#define UU 600
#define PP 30

// W^T in ldmatrix-fragment order, bf16 hi/lo planes.
// half index: ((ktile*4 + plane*2 + mtile)*256) + mat*64 + row*8 + col
//   p = mtile*16 + (mat&1)*8 + row ; k = ktile*16 + ((mat>>1)&1)*8 + col
__device__ __align__(16) uint16_t g_Wf[32768];

__global__ void k0_prepW(const float* __restrict__ W) {
    int i = blockIdx.x * 256 + threadIdx.x;      // 128*256 = 32768
    int col = i & 7, row = (i >> 3) & 7, mat = (i >> 6) & 3;
    int mtile = (i >> 8) & 1, plane = (i >> 9) & 1, ktile = i >> 10;
    int p = mtile * 16 + (mat & 1) * 8 + row;
    int k = ktile * 16 + ((mat >> 1) & 1) * 8 + col;
    float w = (p < PP) ? W[k * PP + p] : 0.f;
    __nv_bfloat16 hi = __float2bfloat16(w);
    __nv_bfloat16 v  = plane ? __float2bfloat16(w - __bfloat162float(hi)) : hi;
    g_Wf[i] = *(uint16_t*)&v;
}

// ---------------- PTX helpers (sm_80-compatible only) ----------------
#define EX2A(d, a) asm("ex2.approx.f32 %0, %1;" : "=f"(d) : "f"(a))

__device__ __forceinline__ void cpa16(uint32_t dst, const void* src) {
    asm volatile("cp.async.cg.shared.global [%0], [%1], 16;" :: "r"(dst), "l"(src));
}
#define CPA_COMMIT() asm volatile("cp.async.commit_group;")
#define CPA_WAIT0()  asm volatile("cp.async.wait_group 0;")

__device__ __forceinline__ uint32_t cvt_pack_bf2(float lo_elem, float hi_elem) {
    uint32_t r;
    asm("cvt.rn.bf16x2.f32 %0, %1, %2;" : "=r"(r) : "f"(hi_elem), "f"(lo_elem));
    return r;
}
__device__ __forceinline__ void ldsm4(uint32_t* r, uint32_t addr) {
    asm volatile("ldmatrix.sync.aligned.m8n8.x4.shared.b16 {%0,%1,%2,%3}, [%4];"
                 : "=r"(r[0]), "=r"(r[1]), "=r"(r[2]), "=r"(r[3]) : "r"(addr));
}
__device__ __forceinline__ void mma16816(float* d, const uint32_t* a,
                                         uint32_t b0, uint32_t b1) {
    asm volatile(
        "mma.sync.aligned.m16n8k16.row.col.f32.bf16.bf16.f32 "
        "{%0,%1,%2,%3},{%4,%5,%6,%7},{%8,%9},{%0,%1,%2,%3};"
        : "+f"(d[0]), "+f"(d[1]), "+f"(d[2]), "+f"(d[3])
        : "r"(a[0]), "r"(a[1]), "r"(a[2]), "r"(a[3]), "r"(b0), "r"(b1));
}

// smem layout (float offsets)
#define W_OFF    0        // 2 bufs x 1024 fl (4KB W-fragment chunk each)
#define X_OFF    2048     // 10240 halves = 5120 fl: [buf][plane][64][40]
#define CH_OFF   0        // phase-B alias: 2 x 1280 fl (over W + X head)
#define PH_OFF   2560     // phase-B alias: 2 x 16*68 = 2176 fl
#define ABK_OFF  7168     // 64*33 = 2112 fl (past X region)
#define BIAS_OFF 9280     // 32 fl
#define UB_OFF   9312
#define SMEM_FLOATS 9316
#define SMEM_BYTES (SMEM_FLOATS * 4)

__global__ __launch_bounds__(256, 2) void fused(
    const float* __restrict__ lstm,
    const float* __restrict__ chs,
    const float* __restrict__ bias,
    float* __restrict__ out)
{
    extern __shared__ float S[];
    int* iUblk = (int*)&S[UB_OFF];
    const int tid  = threadIdx.x;
    const int wid  = tid >> 5;
    const int lane = tid & 31;
    const int row0 = blockIdx.x * 64;
    const int b    = blockIdx.x >> 4;             // 16 CTAs per batch
    const float* lbase = lstm + (size_t)row0 * HH;
    const float* cb    = chs + (size_t)b * UU * AA;
    const uint32_t sbase = (uint32_t)__cvta_generic_to_shared(S);
    uint16_t* Xh = (uint16_t*)&S[X_OFF];

    if (tid == 0) *iUblk = 16;
    if (tid < 32) S[BIAS_OFF + tid] = (tid < PP) ? bias[tid] : 0.f;

    // X staging: warp owns its 8 rows; half-warp = 1 row, 4 iters of 2 rows.
    const int srow = wid * 8 + (lane >> 4);
    const int k2   = lane & 15;                   // float2 index within 32-k chunk
    float2 xv[4];

#define LDGX(c) do {                                                           \
    _Pragma("unroll")                                                          \
    for (int it = 0; it < 4; ++it)                                             \
        xv[it] = *(const float2*)(lbase + (size_t)(srow + 2 * it) * HH         \
                                  + (c) * 32 + k2 * 2);                        \
    } while (0)

#define STSX(bsel) do {                                                        \
    _Pragma("unroll")                                                          \
    for (int it = 0; it < 4; ++it) {                                           \
        int r_ = srow + 2 * it;                                                \
        uint32_t p0 = cvt_pack_bf2(xv[it].x, xv[it].y);                        \
        float h0 = __uint_as_float(p0 << 16);                                  \
        float h1 = __uint_as_float(p0 & 0xFFFF0000u);                          \
        uint32_t q0 = cvt_pack_bf2(xv[it].x - h0, xv[it].y - h1);              \
        *(uint32_t*)&Xh[((bsel) * 2 + 0) * 2560 + r_ * 40 + k2 * 2] = p0;      \
        *(uint32_t*)&Xh[((bsel) * 2 + 1) * 2560 + r_ * 40 + k2 * 2] = q0;      \
    } } while (0)

// W-fragment chunk c (2 ktiles = 4KB) -> buffer bsel
#define CPA_W(c, bsel) \
    cpa16(sbase + (uint32_t)(W_OFF + (bsel) * 1024) * 4u + (uint32_t)tid * 16u, \
          (const char*)g_Wf + (size_t)(c) * 4096 + tid * 16)

    // ---- prologue ----
    CPA_W(0, 0); CPA_COMMIT();
    LDGX(0); STSX(0);
    CPA_WAIT0();
    __syncthreads();

    float acc[2][4];
#pragma unroll
    for (int mt = 0; mt < 2; ++mt)
#pragma unroll
        for (int e = 0; e < 4; ++e) acc[mt][e] = 0.f;

    // ---- GEMM1 main loop: 16 chunks x 2 ktiles; warp does 8t x 30p ----
#pragma unroll 1
    for (int c = 0; c < 16; ++c) {
        const int buf = c & 1;
        if (c + 1 < 16) { LDGX(c + 1); CPA_W(c + 1, buf ^ 1); CPA_COMMIT(); }

#pragma unroll
        for (int kt2 = 0; kt2 < 2; ++kt2) {
            uint32_t A[2][2][4];              // [plane][mtile]
#pragma unroll
            for (int pl = 0; pl < 2; ++pl)
#pragma unroll
                for (int mt = 0; mt < 2; ++mt)
                    ldsm4(A[pl][mt],
                          sbase + (uint32_t)(W_OFF + buf * 1024) * 4u
                                + (uint32_t)(kt2 * 2048 + (pl * 2 + mt) * 512 + lane * 16));
            uint32_t Bf[2][2];                // [plane][b0,b1]
            {
                int t  = wid * 8 + (lane >> 2);
                int kc = kt2 * 16 + (lane & 3) * 2;
#pragma unroll
                for (int pl = 0; pl < 2; ++pl) {
                    const uint16_t* xp = Xh + (buf * 2 + pl) * 2560 + t * 40 + kc;
                    Bf[pl][0] = *(const uint32_t*)xp;
                    Bf[pl][1] = *(const uint32_t*)(xp + 8);
                }
            }
#pragma unroll
            for (int mt = 0; mt < 2; ++mt) {
                mma16816(acc[mt], A[0][mt], Bf[0][0], Bf[0][1]);  // hi*hi
                mma16816(acc[mt], A[0][mt], Bf[1][0], Bf[1][1]);  // hi*lo
                mma16816(acc[mt], A[1][mt], Bf[0][0], Bf[0][1]);  // lo*hi
            }
        }
        if (c + 1 < 16) { STSX(buf ^ 1); CPA_WAIT0(); }
        __syncthreads();
    }

    // ---- CH prefetch chunks 0+1 (W/X regions now free) ----
    {
        uint32_t dst = sbase + (uint32_t)CH_OFF * 4u;
#pragma unroll
        for (int i = 0; i < 3; ++i) {
            int g = tid + 256 * i;
            if (g < 640) cpa16(dst + (uint32_t)g * 16u, cb + g * 4);
        }
        CPA_COMMIT();
    }

    // ---- epilogue: exp(D + bias) -> sABK[t][p] ----
    float* sabk = &S[ABK_OFF];
#pragma unroll
    for (int mt = 0; mt < 2; ++mt)
#pragma unroll
        for (int e = 0; e < 4; ++e) {
            int p = mt * 16 + (lane >> 2) + ((e >= 2) ? 8 : 0);
            int t = wid * 8 + (lane & 3) * 2 + (e & 1);
            if (p < PP)
                sabk[t * 33 + p] = __expf(acc[mt][e] + S[BIAS_OFF + p]);
        }
    __syncthreads();

    // ---- phi setup + cutoff ----
    const int tphi = tid & 63, uh = tid >> 6;     // 4 quarters x 4 u's per chunk
    float ra[10], rbl[10], rk[10];
    float um = 1.f;
#pragma unroll
    for (int m = 0; m < 10; ++m) {
        float av = sabk[tphi * 33 + m];
        float bv = sabk[tphi * 33 + 10 + m];
        float kv = sabk[tphi * 33 + 20 + m];
        ra[m] = av; rk[m] = kv;
        um = fmaxf(um, kv + sqrtf(40.f / bv));
        rbl[m] = -1.4426950408889634f * bv;       // phi term = a * 2^(rbl*d^2)
    }
    if (uh == 0)
        atomicMax(iUblk, (int)fminf(ceilf(um) + 2.f, (float)UU));
    CPA_WAIT0();
    __syncthreads();
    const int nch = (*iUblk + 15) >> 4;

    // ---- windowed phi + GEMM2 (2t x 10a per thread) ----
    const int tg2 = tid & 31, ag = tid >> 5;
    float accO[2][10];
#pragma unroll
    for (int i = 0; i < 2; ++i)
#pragma unroll
        for (int j = 0; j < 10; ++j) accO[i][j] = 0.f;

#pragma unroll 1
    for (int c = 0; c < nch; ++c) {
        const int kb = c & 1;
        if (c >= 2) {   // rare: stage char chunk c (clamped)
            for (int idx = tid; idx < 1280; idx += 256) {
                int u = idx / 80, a = idx - u * 80;
                int gu = c * 16 + u; if (gu >= UU) gu = UU - 1;
                S[CH_OFF + kb * 1280 + idx] = cb[gu * AA + a];
            }
        }
        float* sphi = &S[PH_OFF + kb * 1088];
#pragma unroll
        for (int r = 0; r < 4; ++r) {
            float uf = (float)(c * 16 + uh * 4 + r);
            float s = 0.f;
#pragma unroll
            for (int m = 0; m < 10; ++m) {
                float d = rk[m] - uf;
                float e; EX2A(e, rbl[m] * d * d);
                s = fmaf(ra[m], e, s);
            }
            sphi[(uh * 4 + r) * 68 + tphi] = s;
        }
        __syncthreads();

        const float* sch = &S[CH_OFF + kb * 1280];
#pragma unroll 4
        for (int u = 0; u < 16; ++u) {
            float2 ph = *(const float2*)&sphi[u * 68 + tg2 * 2];
            const float2* cp2 = (const float2*)&sch[u * 80 + ag * 10];
            float2 c01 = cp2[0], c23 = cp2[1], c45 = cp2[2], c67 = cp2[3], c89 = cp2[4];
            float cc[10] = {c01.x, c01.y, c23.x, c23.y, c45.x,
                            c45.y, c67.x, c67.y, c89.x, c89.y};
#pragma unroll
            for (int j = 0; j < 10; ++j) {
                accO[0][j] = fmaf(ph.x, cc[j], accO[0][j]);
                accO[1][j] = fmaf(ph.y, cc[j], accO[1][j]);
            }
        }
        __syncthreads();
    }

    // ---- store ----
#pragma unroll
    for (int i = 0; i < 2; ++i) {
        float* orow = out + (size_t)(row0 + tg2 * 2 + i) * AA + ag * 10;
#pragma unroll
        for (int j2 = 0; j2 < 5; ++j2)
            *(float2*)&orow[j2 * 2] = make_float2(accO[i][2 * j2], accO[i][2 * j2 + 1]);
    }
}

extern "C" void kernel_launch(void* const* d_in, const int* in_sizes, int n_in,
                              void* d_out, int out_size)
{
    const float* lstm = (const float*)d_in[0];  // [16,1024,512]
    const float* chs  = (const float*)d_in[1];  // [16,600,80]
    const float* W    = (const float*)d_in[2];  // [512,30]
    const float* bias = (const float*)d_in[3];  // [30]
    float* out = (float*)d_out;                 // [16,1024,80]
    (void)in_sizes; (void)n_in; (void)out_size;

    cudaFuncSetAttribute(fused, cudaFuncAttributeMaxDynamicSharedMemorySize, SMEM_BYTES);
    k0_prepW<<<128, 256>>>(W);
    fused<<<256, 256, SMEM_BYTES>>>(lstm, chs, bias, out);
}